// round 9
// baseline (speedup 1.0000x reference)
#include <cuda_runtime.h>
#include <math.h>
#include <stdint.h>

#define BB 64
#define RR 8192
#define DD 256

// 8 warps * 4 rows = 32 rows per block; 256 blocks per batch
#define BLKS_PER_BATCH 256

#define EPS_NORM 1e-12f
#define EPS_SUM  1e-8f

// ---------------- device scratch (no allocations allowed) ----------------
__device__ float g_sims[BB * RR];               // cosine sims
__device__ int   g_blkcnt[BB * BLKS_PER_BATCH]; // per-block masked counts
__device__ int   g_idx[BB * RR];                // compacted indices (rare path)
__device__ float g_w[BB * RR];                  // compacted normalized weights

__device__ __forceinline__ float sigmoid_acc(float x) {
    return 1.0f / (1.0f + expf(-x));
}

__device__ __forceinline__ int clip_q(long long qq) {
    return (int)(qq < 0 ? 0 : (qq > (RR - 1) ? (RR - 1) : qq));
}

// ---------------- kernel B: fused qnorm + copy + cosine sims + mask count ----
// Grid = BB*256 blocks, 256 threads (8 warps), 4 rows/warp.
// __launch_bounds__(256, 8): cap regs at 32 -> 8 blocks/SM (100% occupancy).
__global__ void __launch_bounds__(256, 8) kB(const float* __restrict__ in,
                                             float* __restrict__ out,
                                             const long long* __restrict__ qrels,
                                             const float* __restrict__ thrp)
{
    __shared__ float s_qn[DD];
    __shared__ float s_red[8];
    __shared__ int   s_icnt[8];

    const int t    = threadIdx.x;
    const int warp = t >> 5;
    const int lane = t & 31;
    const int b = blockIdx.x >> 8;                 // 256 blocks per batch
    const int rowBase = (blockIdx.x & 255) * 32;

    const int q = clip_q(qrels[b]);

    // --- per-block query-row normalization (1 KB from L2, redundant, cheap) ---
    float v = in[((size_t)b * RR + q) * DD + t];
    float s = v * v;
    #pragma unroll
    for (int o = 16; o > 0; o >>= 1) s += __shfl_xor_sync(0xffffffffu, s, o);
    if (lane == 0) s_red[warp] = s;
    __syncthreads();
    if (t < 8) {
        float x = s_red[t];
        #pragma unroll
        for (int o = 4; o > 0; o >>= 1) x += __shfl_xor_sync(0xffu, x, o);
        if (t == 0) s_red[0] = x;
    }
    __syncthreads();
    const float invn = 1.0f / fmaxf(sqrtf(s_red[0]), EPS_NORM);
    s_qn[t] = v * invn;
    __syncthreads();

    const float4* qn4 = (const float4*)s_qn;
    const float4 q0 = qn4[lane];
    const float4 q1 = qn4[lane + 32];

    const float thr = sigmoid_acc(thrp[0]);

    // streaming: 4 contiguous rows per warp (no manual double-buffer; ptxas
    // hoists the independent next-row loads — keeps regs under the 32 cap)
    const int warpRow0 = rowBase + warp * 4;
    const size_t base4 = ((size_t)b * RR + warpRow0) * (DD / 4);
    const float4* ip = (const float4*)in + base4;
    float4*       op = (float4*)out + base4;

    int cnt = 0;
    #pragma unroll
    for (int i = 0; i < 4; i++) {
        float4 a0 = __ldcs(ip + i * 64 + lane);
        float4 a1 = __ldcs(ip + i * 64 + lane + 32);
        __stcs(op + i * 64 + lane,      a0);
        __stcs(op + i * 64 + lane + 32, a1);

        float ss = a0.x*a0.x + a0.y*a0.y + a0.z*a0.z + a0.w*a0.w
                 + a1.x*a1.x + a1.y*a1.y + a1.z*a1.z + a1.w*a1.w;
        float dp = a0.x*q0.x + a0.y*q0.y + a0.z*q0.z + a0.w*q0.w
                 + a1.x*q1.x + a1.y*q1.y + a1.z*q1.z + a1.w*q1.w;

        #pragma unroll
        for (int o = 16; o > 0; o >>= 1) {
            ss += __shfl_xor_sync(0xffffffffu, ss, o);
            dp += __shfl_xor_sync(0xffffffffu, dp, o);
        }
        const int row = warpRow0 + i;
        float sim = dp / fmaxf(sqrtf(ss), EPS_NORM);
        sim = (row == q) ? -1.0f : sim;        // all lanes hold full sums
        if (lane == 0) g_sims[(size_t)b * RR + row] = sim;
        cnt += (sim > thr) ? 1 : 0;
    }

    if (lane == 0) s_icnt[warp] = cnt;
    __syncthreads();
    if (t == 0) {
        int c = 0;
        #pragma unroll
        for (int w = 0; w < 8; w++) c += s_icnt[w];
        g_blkcnt[blockIdx.x] = c;   // plain store: deterministic, replay-safe
    }

    cudaTriggerProgrammaticLaunchCompletion();
}

// ---------------- kernel T: per-batch tail (cheap common path, PDL) ----------
__global__ void __launch_bounds__(256) kT(const float* __restrict__ in,
                                          float* __restrict__ out,
                                          const long long* __restrict__ qrels,
                                          const float* __restrict__ thrp,
                                          const float* __restrict__ strp,
                                          const float* __restrict__ scalep,
                                          const float* __restrict__ tempp)
{
    __shared__ float s_red[8];
    __shared__ int   s_ired[8];

    const int b    = blockIdx.x;
    const int t    = threadIdx.x;
    const int warp = t >> 5;
    const int lane = t & 31;

    cudaGridDependencySynchronize();

    // --- common path: reduce per-block counts (1 KB from L2) ---
    int cnt = g_blkcnt[b * BLKS_PER_BATCH + t];
    int ctot;
    {
        int x = cnt;
        #pragma unroll
        for (int o = 16; o > 0; o >>= 1) x += __shfl_xor_sync(0xffffffffu, x, o);
        if (lane == 0) s_ired[warp] = x;
        __syncthreads();
        if (t < 8) {
            int y = s_ired[t];
            #pragma unroll
            for (int o = 4; o > 0; o >>= 1) y += __shfl_xor_sync(0xffu, y, o);
            if (t == 0) s_ired[0] = y;
        }
        __syncthreads();
        ctot = s_ired[0];
    }
    if (ctot == 0) return;   // out row q already == qrep (kB copy)

    // ================= rare path: mask nonempty =================
    const float thr      = sigmoid_acc(thrp[0]);
    const float strength = sigmoid_acc(strp[0]) * 0.2f;
    const float temp     = fminf(fmaxf(tempp[0], 0.1f), 10.0f);
    const float scale    = scalep[0];
    const float invT     = 1.0f / temp;
    const int   q        = clip_q(qrels[b]);

    const float* __restrict__ simsB = g_sims + (size_t)b * RR;

    // fused ES/AS + per-thread count on strided layout (i = t + k*256).
    // No softmax shift needed: s <= 1 -> exp(s/temp) <= e^10, safe.
    float es = 0.0f, as = 0.0f;
    int   mycnt = 0;
    for (int i = t; i < RR; i += 256) {
        float s = simsB[i];
        if (s > thr) {
            float e  = expf(s * invT);
            float sw = 1.0f / (1.0f + expf(-(s - thr) * 10.0f));
            es += e;
            as += e * sw * (1.0f + scale * s);
            mycnt++;
        }
    }
    float ES, AS;
    {
        float x = es, y = as;
        #pragma unroll
        for (int o = 16; o > 0; o >>= 1) {
            x += __shfl_xor_sync(0xffffffffu, x, o);
            y += __shfl_xor_sync(0xffffffffu, y, o);
        }
        __syncthreads();
        if (lane == 0) s_red[warp] = x;
        __syncthreads();
        if (t < 8) {
            float z = s_red[t];
            #pragma unroll
            for (int o = 4; o > 0; o >>= 1) z += __shfl_xor_sync(0xffu, z, o);
            if (t == 0) s_red[0] = z;
        }
        __syncthreads();
        ES = s_red[0];
        __syncthreads();
        if (lane == 0) s_red[warp] = y;
        __syncthreads();
        if (t < 8) {
            float z = s_red[t];
            #pragma unroll
            for (int o = 4; o > 0; o >>= 1) z += __shfl_xor_sync(0xffu, z, o);
            if (t == 0) s_red[0] = z;
        }
        __syncthreads();
        AS = s_red[0];
    }
    const float C = 1.0f / (AS + EPS_SUM * ES);

    // exclusive offset: warp shuffle scan + cross-warp scan
    int myOff;
    {
        int inc = mycnt;
        #pragma unroll
        for (int o = 1; o < 32; o <<= 1) {
            int y = __shfl_up_sync(0xffffffffu, inc, o);
            if (lane >= o) inc += y;
        }
        __syncthreads();
        if (lane == 31) s_ired[warp] = inc;
        __syncthreads();
        if (t < 8) {
            int vv = s_ired[t];
            #pragma unroll
            for (int o = 1; o < 8; o <<= 1) {
                int y = __shfl_up_sync(0xffu, vv, o);
                if (t >= o) vv += y;
            }
            s_ired[t] = vv;
        }
        __syncthreads();
        int warpBase = (warp == 0) ? 0 : s_ired[warp - 1];
        myOff = warpBase + inc - mycnt;
    }

    // compaction (deterministic fixed order) into global scratch (L2-resident)
    int pos = myOff;
    for (int i = t; i < RR; i += 256) {
        float s = simsB[i];
        if (s > thr) {
            float e  = expf(s * invT);
            float sw = 1.0f / (1.0f + expf(-(s - thr) * 10.0f));
            g_idx[(size_t)b * RR + pos] = i;
            g_w [(size_t)b * RR + pos] = e * sw * (1.0f + scale * s) * C;
            pos++;
        }
    }
    __syncthreads();
    __threadfence_block();

    // epilogue: rewrite row q (t == d, DD == 256)
    float acc = 0.0f;
    for (int i = 0; i < ctot; i++) {
        int   r = g_idx[(size_t)b * RR + i];
        float w = g_w [(size_t)b * RR + i];
        acc += w * in[((size_t)b * RR + r) * DD + t];
    }
    float qv = in[((size_t)b * RR + q) * DD + t];
    out[((size_t)b * RR + q) * DD + t] = (1.0f - strength) * qv + strength * acc;
}

// ---------------- launch ----------------
extern "C" void kernel_launch(void* const* d_in, const int* in_sizes, int n_in,
                              void* d_out, int out_size)
{
    const float*     reps  = (const float*)d_in[0];
    const long long* qrels = (const long long*)d_in[1];
    const float*     thrp  = (const float*)d_in[2];
    const float*     strp  = (const float*)d_in[3];
    const float*     sclp  = (const float*)d_in[4];
    const float*     tmpp  = (const float*)d_in[5];
    float* out = (float*)d_out;

    kB<<<BB * BLKS_PER_BATCH, 256>>>(reps, out, qrels, thrp);

    cudaLaunchConfig_t cfg = {};
    cfg.gridDim  = dim3(BB, 1, 1);
    cfg.blockDim = dim3(256, 1, 1);
    cfg.dynamicSmemBytes = 0;
    cfg.stream = 0;
    cudaLaunchAttribute attrs[1];
    attrs[0].id = cudaLaunchAttributeProgrammaticStreamSerialization;
    attrs[0].val.programmaticStreamSerializationAllowed = 1;
    cfg.attrs = attrs;
    cfg.numAttrs = 1;
    cudaLaunchKernelEx(&cfg, kT, reps, out, qrels, thrp, strp, sclp, tmpp);
}

// round 10
// speedup vs baseline: 1.0162x; 1.0162x over previous
#include <cuda_runtime.h>
#include <math.h>
#include <stdint.h>

#define BB 64
#define RR 8192
#define DD 256

#define EPS_NORM 1e-12f
#define EPS_SUM  1e-8f

// ---------------- device scratch (no allocations allowed) ----------------
__device__ float    g_sims[BB * RR];   // cosine sims
__device__ unsigned g_pack[BB];        // packed {count<<9 | arrivals}; self-resetting
__device__ int      g_idx[BB * RR];    // compacted indices (rare path)
__device__ float    g_w[BB * RR];      // compacted normalized weights

__device__ __forceinline__ float sigmoid_acc(float x) {
    return 1.0f / (1.0f + expf(-x));
}

__device__ __forceinline__ int clip_q(long long qq) {
    return (int)(qq < 0 ? 0 : (qq > (RR - 1) ? (RR - 1) : qq));
}

// ---------------- single kernel: R5 hot loop + reg-capped inline tail --------
// Grid = BB*256 blocks, 256 threads (8 warps), 4 rows/warp, double-buffered.
// __launch_bounds__(256, 6): <=42 regs -> 6 blocks/SM, same residency as the
// best measured streaming config (R5 kB, 40 regs). Tail path may spill; it
// runs on at most 64 blocks and (for typical data) exits immediately.
__global__ void __launch_bounds__(256, 6) kF(const float* __restrict__ in,
                                             float* __restrict__ out,
                                             const long long* __restrict__ qrels,
                                             const float* __restrict__ thrp,
                                             const float* __restrict__ strp,
                                             const float* __restrict__ scalep,
                                             const float* __restrict__ tempp)
{
    __shared__ float s_qn[DD];
    __shared__ float s_red[8];
    __shared__ int   s_icnt[8];
    __shared__ unsigned s_old;

    const int t    = threadIdx.x;
    const int warp = t >> 5;
    const int lane = t & 31;
    const int b = blockIdx.x >> 8;                 // 256 blocks per batch
    const int rowBase = (blockIdx.x & 255) * 32;

    const int q = clip_q(qrels[b]);

    // --- per-block query-row normalization (1 KB from L2, redundant, cheap) ---
    float v = in[((size_t)b * RR + q) * DD + t];
    float s = v * v;
    #pragma unroll
    for (int o = 16; o > 0; o >>= 1) s += __shfl_xor_sync(0xffffffffu, s, o);
    if (lane == 0) s_red[warp] = s;
    __syncthreads();
    if (t < 8) {
        float x = s_red[t];
        #pragma unroll
        for (int o = 4; o > 0; o >>= 1) x += __shfl_xor_sync(0xffu, x, o);
        if (t == 0) s_red[0] = x;
    }
    __syncthreads();
    const float invn = 1.0f / fmaxf(sqrtf(s_red[0]), EPS_NORM);
    s_qn[t] = v * invn;
    __syncthreads();

    const float4* qn4 = (const float4*)s_qn;
    const float4 q0 = qn4[lane];
    const float4 q1 = qn4[lane + 32];

    const float thr = sigmoid_acc(thrp[0]);

    // --- streaming hot loop: 4 contiguous rows per warp, double-buffered ---
    const size_t base4 = ((size_t)b * RR + rowBase + warp * 4) * (DD / 4);
    const float4* ip = (const float4*)in + base4;
    float4*       op = (float4*)out + base4;

    float4 a0 = __ldcs(ip + lane);
    float4 a1 = __ldcs(ip + lane + 32);

    int cnt = 0;
    #pragma unroll
    for (int i = 0; i < 4; i++) {
        float4 n0, n1;
        if (i < 3) {
            n0 = __ldcs(ip + (i + 1) * 64 + lane);
            n1 = __ldcs(ip + (i + 1) * 64 + lane + 32);
        }
        __stcs(op + i * 64 + lane,      a0);
        __stcs(op + i * 64 + lane + 32, a1);

        float ss = a0.x*a0.x + a0.y*a0.y + a0.z*a0.z + a0.w*a0.w
                 + a1.x*a1.x + a1.y*a1.y + a1.z*a1.z + a1.w*a1.w;
        float dp = a0.x*q0.x + a0.y*q0.y + a0.z*q0.z + a0.w*q0.w
                 + a1.x*q1.x + a1.y*q1.y + a1.z*q1.z + a1.w*q1.w;

        #pragma unroll
        for (int o = 16; o > 0; o >>= 1) {
            ss += __shfl_xor_sync(0xffffffffu, ss, o);
            dp += __shfl_xor_sync(0xffffffffu, dp, o);
        }
        const int row = rowBase + warp * 4 + i;
        float sim = dp / fmaxf(sqrtf(ss), EPS_NORM);
        sim = (row == q) ? -1.0f : sim;            // all lanes hold full sums
        if (lane == 0) g_sims[(size_t)b * RR + row] = sim;
        cnt += (sim > thr) ? 1 : 0;

        a0 = n0; a1 = n1;
    }

    // --- block count + packed arrival atomic (last block runs the tail) ---
    if (lane == 0) s_icnt[warp] = cnt;
    __syncthreads();
    int blkcnt = s_icnt[0] + s_icnt[1] + s_icnt[2] + s_icnt[3]
               + s_icnt[4] + s_icnt[5] + s_icnt[6] + s_icnt[7];

    const bool ownsQ = (q >= rowBase) && (q < rowBase + 32);
    // Fence ONLY when this block's data must be visible to a potential tail:
    //  - blkcnt > 0: its g_sims entries participate in the masked softmax
    //  - ownsQ: its copy of out-row-q must be ordered before a tail overwrite
    // Common case (empty mask): 16320/16384 blocks skip the fence entirely.
    if (blkcnt > 0 || ownsQ) __threadfence();
    __syncthreads();

    if (t == 0) s_old = atomicAdd(&g_pack[b], ((unsigned)blkcnt << 9) | 1u);
    __syncthreads();
    const unsigned old = s_old;
    if ((old & 511u) != 255u) return;          // not the last block of batch b

    const int total = (int)(old >> 9) + blkcnt;
    if (t == 0) atomicExch(&g_pack[b], 0u);    // reset for next graph replay
    if (total == 0) return;                    // out row q already == qrep

    // ================= rare path (may spill; executes ~never) ================
    const float strength = sigmoid_acc(strp[0]) * 0.2f;
    const float temp     = fminf(fmaxf(tempp[0], 0.1f), 10.0f);
    const float scale    = scalep[0];
    const float invT     = 1.0f / temp;

    const float* __restrict__ simsB = g_sims + (size_t)b * RR;

    // fused ES/AS + per-thread count (strided layout i = t + k*256).
    // No softmax shift needed: s <= 1 -> exp(s/temp) <= e^10, safe.
    float es = 0.0f, as = 0.0f;
    int   mycnt = 0;
    for (int i = t; i < RR; i += 256) {
        float sv = simsB[i];
        if (sv > thr) {
            float e  = expf(sv * invT);
            float sw = 1.0f / (1.0f + expf(-(sv - thr) * 10.0f));
            es += e;
            as += e * sw * (1.0f + scale * sv);
            mycnt++;
        }
    }
    float ES, AS;
    {
        float x = es, y = as;
        #pragma unroll
        for (int o = 16; o > 0; o >>= 1) {
            x += __shfl_xor_sync(0xffffffffu, x, o);
            y += __shfl_xor_sync(0xffffffffu, y, o);
        }
        __syncthreads();
        if (lane == 0) s_red[warp] = x;
        __syncthreads();
        if (t < 8) {
            float z = s_red[t];
            #pragma unroll
            for (int o = 4; o > 0; o >>= 1) z += __shfl_xor_sync(0xffu, z, o);
            if (t == 0) s_red[0] = z;
        }
        __syncthreads();
        ES = s_red[0];
        __syncthreads();
        if (lane == 0) s_red[warp] = y;
        __syncthreads();
        if (t < 8) {
            float z = s_red[t];
            #pragma unroll
            for (int o = 4; o > 0; o >>= 1) z += __shfl_xor_sync(0xffu, z, o);
            if (t == 0) s_red[0] = z;
        }
        __syncthreads();
        AS = s_red[0];
    }
    const float C = 1.0f / (AS + EPS_SUM * ES);

    // exclusive offset: warp shuffle scan + cross-warp scan
    int myOff;
    {
        int inc = mycnt;
        #pragma unroll
        for (int o = 1; o < 32; o <<= 1) {
            int y2 = __shfl_up_sync(0xffffffffu, inc, o);
            if (lane >= o) inc += y2;
        }
        __syncthreads();
        if (lane == 31) s_icnt[warp] = inc;
        __syncthreads();
        if (t < 8) {
            int vv = s_icnt[t];
            #pragma unroll
            for (int o = 1; o < 8; o <<= 1) {
                int y2 = __shfl_up_sync(0xffu, vv, o);
                if (t >= o) vv += y2;
            }
            s_icnt[t] = vv;
        }
        __syncthreads();
        int warpBase = (warp == 0) ? 0 : s_icnt[warp - 1];
        myOff = warpBase + inc - mycnt;
    }

    // compaction (deterministic fixed order) into global scratch (L2-resident)
    int pos = myOff;
    for (int i = t; i < RR; i += 256) {
        float sv = simsB[i];
        if (sv > thr) {
            float e  = expf(sv * invT);
            float sw = 1.0f / (1.0f + expf(-(sv - thr) * 10.0f));
            g_idx[(size_t)b * RR + pos] = i;
            g_w [(size_t)b * RR + pos] = e * sw * (1.0f + scale * sv) * C;
            pos++;
        }
    }
    __syncthreads();
    __threadfence_block();

    // epilogue: rewrite row q (t == d, DD == 256)
    float acc = 0.0f;
    for (int i = 0; i < total; i++) {
        int   r = g_idx[(size_t)b * RR + i];
        float w = g_w [(size_t)b * RR + i];
        acc += w * in[((size_t)b * RR + r) * DD + t];
    }
    float qv = in[((size_t)b * RR + q) * DD + t];
    out[((size_t)b * RR + q) * DD + t] = (1.0f - strength) * qv + strength * acc;
}

// ---------------- launch ----------------
extern "C" void kernel_launch(void* const* d_in, const int* in_sizes, int n_in,
                              void* d_out, int out_size)
{
    const float*     reps  = (const float*)d_in[0];
    const long long* qrels = (const long long*)d_in[1];
    const float*     thrp  = (const float*)d_in[2];
    const float*     strp  = (const float*)d_in[3];
    const float*     sclp  = (const float*)d_in[4];
    const float*     tmpp  = (const float*)d_in[5];
    float* out = (float*)d_out;

    kF<<<BB * 256, 256>>>(reps, out, qrels, thrp, strp, sclp, tmpp);
}